// round 6
// baseline (speedup 1.0000x reference)
#include <cuda_runtime.h>
#include <math.h>

#define BB 2
#define NN 8192
#define NPT (BB*NN)
#define KNN 10
#define GRID 16
#define GC (GRID*GRID*GRID)
#define HCELL 0.0625f
#define NBLK 128
#define NTG 512
#define SCAP 2048

// ---------------- device scratch ----------------
__device__ float4 g_sp4[NPT];        // sorted points (x,y,z, sq with sign bit = mask)
__device__ int    g_sidx[NPT];       // sorted -> original index
__device__ int    g_cnt[BB*GC];      // INVARIANT: zero at kernel entry (re-zeroed each call)
__device__ int2   g_range[BB*GC];    // (start,end) within batch
__device__ int    g_cur[BB*GC];
__device__ double g_cacc[BB][4];     // masked centroid sums + count (zeroed in-phase each call)
__device__ float  g_geom[NPT * 6];
__device__ int    g_mtype;           // monotone OR of same data -> stable across calls
__device__ float  g_T;
__device__ unsigned g_barcnt = 0;
__device__ unsigned g_sense  = 0;

// ---------------- grid barrier (128 co-resident blocks) ----------------
__device__ __forceinline__ void gridbar() {
    __syncthreads();
    if (threadIdx.x == 0) {
        __threadfence();
        unsigned gen = atomicAdd(&g_sense, 0u);
        if (atomicAdd(&g_barcnt, 1u) == NBLK - 1) {
            g_barcnt = 0;
            __threadfence();
            atomicAdd(&g_sense, 1u);
        } else {
            while (atomicAdd(&g_sense, 0u) == gen) {}
        }
        __threadfence();
    }
    __syncthreads();
}

// ---------------- f32x2 helpers ----------------
#define FMA2(d, a, b) asm("fma.rn.f32x2 %0, %1, %2, %3;" : "=l"(d) : "l"(a), "l"(b), "l"(d))
__device__ __forceinline__ unsigned long long pack2(float v) {
    unsigned long long r; unsigned u = __float_as_uint(v);
    asm("mov.b64 %0, {%1, %1};" : "=l"(r) : "r"(u));
    return r;
}
__device__ __forceinline__ void unpack2(unsigned long long v, float& lo, float& hi) {
    unsigned a, b;
    asm("mov.b64 {%0, %1}, %2;" : "=r"(a), "=r"(b) : "l"(v));
    lo = __uint_as_float(a); hi = __uint_as_float(b);
}

__device__ __forceinline__ int cell_of(float x, float y, float z) {
    int cx = min(GRID - 1, max(0, (int)(x * (float)GRID)));
    int cy = min(GRID - 1, max(0, (int)(y * (float)GRID)));
    int cz = min(GRID - 1, max(0, (int)(z * (float)GRID)));
    return (cz * GRID + cy) * GRID + cx;
}

__device__ __forceinline__ bool read_mask(const void* mp, int i, int mt) {
    if (mt & 1) return ((const unsigned char*)mp)[i] != 0;
    if (mt & 2) return ((const float*)mp)[i] != 0.0f;
    return ((const int*)mp)[i] != 0;
}

// ---------------- analytic eigenvalues of symmetric 3x3 (fp64) ----------------
__device__ __forceinline__ float curv_from_cov(float c00, float c01, float c02,
                                               float c11, float c12, float c22) {
    double a00 = c00, a01 = c01, a02 = c02, a11 = c11, a12 = c12, a22 = c22;
    double p1 = a01 * a01 + a02 * a02 + a12 * a12;
    double q  = (a00 + a11 + a22) / 3.0;
    double d0 = a00 - q, d1 = a11 - q, d2v = a22 - q;
    double p2 = d0 * d0 + d1 * d1 + d2v * d2v + 2.0 * p1;
    double emin, emax;
    if (!(p2 > 0.0)) { emin = q; emax = q; }
    else {
        double p = sqrt(p2 / 6.0);
        double ip = 1.0 / p;
        double b00 = d0 * ip, b11 = d1 * ip, b22 = d2v * ip;
        double b01 = a01 * ip, b02 = a02 * ip, b12 = a12 * ip;
        double detB = b00 * (b11 * b22 - b12 * b12)
                    - b01 * (b01 * b22 - b12 * b02)
                    + b02 * (b01 * b12 - b11 * b02);
        double r = 0.5 * detB;
        r = fmin(1.0, fmax(-1.0, r));
        double phi = acos(r) / 3.0;
        emax = q + 2.0 * p * cos(phi);
        emin = q + 2.0 * p * cos(phi + 2.0943951023931953);
    }
    float e0 = (float)emin, e2 = (float)emax;
    return e0 / (e2 + 1e-8f);
}

// candidate evaluation (shared by smem + global paths)
#define CAND(PJ, JJ) do {                                                        \
    float sqj = fabsf((PJ).w);                                                   \
    float Tv  = (__float_as_uint((PJ).w) & 0x80000000u)                          \
                ? Tloc : __int_as_float(0xff800000);                             \
    float dot = fmaf(pix, (PJ).x, fmaf(piy, (PJ).y, piz * (PJ).z));              \
    float d2  = fmaf(-2.0f, dot, piw + sqj);                                     \
    if (d2 <= Tv) cnt++;                                                         \
    float d2c = fmaxf(d2, 0.0f);                                                 \
    if (d2c < t_est) passes++;                                                   \
    unsigned long long key =                                                     \
        ((unsigned long long)__float_as_uint(d2c) << 32) | (unsigned)(JJ);       \
    if (key < best[KNN - 1]) {                                                   \
        _Pragma("unroll")                                                        \
        for (int _k = 0; _k < KNN; _k++) {                                       \
            if (key < best[_k]) {                                                \
                unsigned long long _t = best[_k]; best[_k] = key; key = _t;      \
            }                                                                    \
        }                                                                        \
    }                                                                            \
} while (0)

// ================= kernel 1: prep (gridbar phases) + region-tiled geom =================
__global__ void __launch_bounds__(NTG)
k_main(const float* __restrict__ pts, const void* __restrict__ mask) {
    __shared__ float4 spt[SCAP];       // region points                (32 KB)
    __shared__ int    sj[SCAP];        // their sorted indices / scan scratch (8 KB)
    __shared__ int2   scell[512];      // per-cell smem ranges          (4 KB)
    __shared__ int    rowjst[64], rowlen[64], rowbase[64];
    __shared__ int    hjst[16], hlen[16], hpre[17];
    __shared__ int    sTotal;

    const int tid = threadIdx.x;
    const int bid = blockIdx.x;
    const int gid = bid * NTG + tid;

    // ---------- phase 1: cell counts + mask dtype detect (g_cnt zero on entry) ----------
    {
        bool act = gid < NPT;
        unsigned char mb = 0;
        if (act) {
            float x = pts[gid * 3 + 0], y = pts[gid * 3 + 1], z = pts[gid * 3 + 2];
            mb = ((const unsigned char*)mask)[gid];
            atomicAdd(&g_cnt[(gid >> 13) * GC + cell_of(x, y, z)], 1);
        }
        int r = gid & 3;
        unsigned m1 = __ballot_sync(0xFFFFFFFFu, act && (r == 1) && mb);
        unsigned m2 = __ballot_sync(0xFFFFFFFFu, act && (r >= 2) && mb);
        if ((tid & 31) == 0 && (m1 | m2))
            atomicOr(&g_mtype, (m1 ? 1 : 0) | (m2 ? 2 : 0));
    }
    gridbar();

    // ---------- phase 2: scan (blocks 0,1) + re-zero g_cnt + zero g_cacc + g_T ----------
    if (bid < BB) {
        int* part = sj;
        int base = bid * GC + tid * 8;
        int loc[8]; int s = 0;
#pragma unroll
        for (int k = 0; k < 8; k++) { loc[k] = s; s += g_cnt[base + k]; }
        part[tid] = s;
        __syncthreads();
        for (int d = 1; d < NTG; d <<= 1) {
            int v = (tid >= d) ? part[tid - d] : 0;
            __syncthreads();
            part[tid] += v;
            __syncthreads();
        }
        int off = part[tid] - s;
#pragma unroll
        for (int k = 0; k < 8; k++) {
            int st = off + loc[k];
            int ln = g_cnt[base + k];
            g_range[base + k] = make_int2(st, st + ln);
            g_cur[base + k]   = st;
            g_cnt[base + k]   = 0;                 // restore invariant
        }
        if (gid == 0) {
            for (int b = 0; b < BB; b++)
                for (int c = 0; c < 4; c++) g_cacc[b][c] = 0.0;
            const float R = 0.02f;
            float t = __fmul_rn(R, R);
            while (__fsqrt_rn(t) >= R) t = __uint_as_float(__float_as_uint(t) - 1u);
            for (;;) {
                float nt = __uint_as_float(__float_as_uint(t) + 1u);
                if (__fsqrt_rn(nt) < R) t = nt; else break;
            }
            g_T = t;
        }
    }
    gridbar();

    // ---------- phase 3: scatter + masked centroid ----------
    if (gid < NPT) {
        int mt = g_mtype;
        float x = pts[gid * 3 + 0], y = pts[gid * 3 + 1], z = pts[gid * 3 + 2];
        float sq = __fadd_rn(__fadd_rn(__fmul_rn(x, x), __fmul_rn(y, y)), __fmul_rn(z, z));
        int b = gid >> 13;
        int cell = b * GC + cell_of(x, y, z);
        bool mk = read_mask(mask, gid, mt);
        float wv = mk ? __uint_as_float(__float_as_uint(sq) | 0x80000000u) : sq;
        int pos = atomicAdd(&g_cur[cell], 1);
        int dst = b * NN + pos;
        g_sp4[dst]  = make_float4(x, y, z, wv);
        g_sidx[dst] = gid;
        double vx = mk ? (double)x : 0.0, vy = mk ? (double)y : 0.0;
        double vz = mk ? (double)z : 0.0, vc = mk ? 1.0 : 0.0;
#pragma unroll
        for (int o = 16; o > 0; o >>= 1) {
            vx += __shfl_down_sync(0xFFFFFFFFu, vx, o);
            vy += __shfl_down_sync(0xFFFFFFFFu, vy, o);
            vz += __shfl_down_sync(0xFFFFFFFFu, vz, o);
            vc += __shfl_down_sync(0xFFFFFFFFu, vc, o);
        }
        if ((tid & 31) == 0) {
            atomicAdd(&g_cacc[b][0], vx);
            atomicAdd(&g_cacc[b][1], vy);
            atomicAdd(&g_cacc[b][2], vz);
            atomicAdd(&g_cacc[b][3], vc);
        }
    }
    gridbar();

    // ---------- phase 4: region-tiled exact 10-NN + density ----------
    const int b   = bid >> 6;
    const int rid = bid & 63;
    const int hx0 = (rid & 3) * 4, hy0 = ((rid >> 2) & 3) * 4, hz0 = (rid >> 4) * 4;
    const int gx0 = max(hx0 - 2, 0), gx1 = min(hx0 + 5, GRID - 1);
    const int gy0 = max(hy0 - 2, 0), gy1 = min(hy0 + 5, GRID - 1);
    const int gz0 = max(hz0 - 2, 0), gz1 = min(hz0 + 5, GRID - 1);
    const int nx = gx1 - gx0 + 1, ny = gy1 - gy0 + 1, nz = gz1 - gz0 + 1;
    const int nrow = ny * nz;
    const int boff = b * NN, cbase = b * GC;
    const float Tloc = g_T;

    // region row ranges + home row ranges
    if (tid < nrow) {
        int z = gz0 + tid / ny, y = gy0 + tid % ny;
        int crow = cbase + (z * GRID + y) * GRID;
        int jst = g_range[crow + gx0].x;
        int jen = g_range[crow + gx1].y;
        rowjst[tid] = jst;
        rowlen[tid] = jen - jst;
    }
    if (tid >= 64 && tid < 80) {
        int hr = tid - 64;
        int z = hz0 + (hr >> 2), y = hy0 + (hr & 3);
        int crow = cbase + (z * GRID + y) * GRID;
        int jst = g_range[crow + hx0].x;
        hjst[hr] = jst;
        hlen[hr] = g_range[crow + hx0 + 3].y - jst;
    }
    __syncthreads();
    if (tid == 0) {
        int acc = 0;
        for (int r = 0; r < nrow; r++) { int l = rowlen[r]; rowbase[r] = acc; acc += l; }
        sTotal = acc;
    }
    if (tid == 1) {
        int acc = 0;
        for (int r = 0; r < 16; r++) { hpre[r] = acc; acc += hlen[r]; }
        hpre[16] = acc;
    }
    __syncthreads();
    const bool ovf = sTotal > SCAP;

    if (!ovf) {
        // copy region points into smem (one warp per row, round-robin)
        int w = tid >> 5, lane = tid & 31;
        for (int rr = w; rr < nrow; rr += 16) {
            int jst = rowjst[rr], len = rowlen[rr], rb = rowbase[rr];
            for (int k = lane; k < len; k += 32) {
                spt[rb + k] = g_sp4[boff + jst + k];
                sj [rb + k] = jst + k;
            }
        }
        // per-cell smem ranges
        for (int c = tid; c < nrow * nx; c += NTG) {
            int rr = c / nx, lx = c % nx;
            int z = gz0 + rr / ny, y = gy0 + rr % ny;
            int2 gr = g_range[cbase + (z * GRID + y) * GRID + gx0 + lx];
            int sh = rowbase[rr] - rowjst[rr];
            scell[rr * 8 + lx] = make_int2(gr.x + sh, gr.y + sh);
        }
    }
    __syncthreads();

    const int M = hpre[16];
    const int grp = tid >> 2, l4 = tid & 3;
    const unsigned gm = 0xFu << ((tid & 31) & ~3);

    for (int task = grp; task < M; task += NTG / 4) {
        int hr = 0;
        while (task >= hpre[hr + 1]) hr++;
        int jp = hjst[hr] + task - hpre[hr];

        float4 pi = g_sp4[boff + jp];
        const float pix = pi.x, piy = pi.y, piz = pi.z, piw = fabsf(pi.w);

        const int cix = min(GRID - 1, max(0, (int)(pix * (float)GRID)));
        const int ciy = min(GRID - 1, max(0, (int)(piy * (float)GRID)));
        const int ciz = min(GRID - 1, max(0, (int)(piz * (float)GRID)));

        // statistical gate: ~22 expected neighbors, wall-clip aware
        float r_est = 0.075f;
#pragma unroll
        for (int it = 0; it < 2; it++) {
            float fx = (fminf(pix + r_est, 1.0f) - fmaxf(pix - r_est, 0.0f)) / (2.0f * r_est);
            float fy = (fminf(piy + r_est, 1.0f) - fmaxf(piy - r_est, 0.0f)) / (2.0f * r_est);
            float fz = (fminf(piz + r_est, 1.0f) - fmaxf(piz - r_est, 0.0f)) / (2.0f * r_est);
            r_est = cbrtf(6.4e-4f / fmaxf(fx * fy * fz, 0.125f));
        }
        const float t_est = r_est * r_est;
        const unsigned long long GATE_EST =
            ((unsigned long long)__float_as_uint(t_est) << 32) | 0xFFFFFFFFull;
        const unsigned long long GATE_INF = 0xFFFFFFFFFFFFFFFFull;

        unsigned long long best[KNN];
        int cnt;
        float c00, c01, c02, c11, c12, c22;
        unsigned long long d10key;

        for (int R = 2;; R++) {
            unsigned long long ginit = (R == 2) ? GATE_EST : GATE_INF;

            for (;;) {   // gate attempt / retry
#pragma unroll
                for (int k = 0; k < KNN; k++) best[k] = ginit;
                cnt = 0;
                int passes = 0;

                const int x0 = max(cix - R, 0), x1 = min(cix + R, GRID - 1);
                const int y0 = max(ciy - R, 0), y1 = min(ciy + R, GRID - 1);
                const int z0 = max(ciz - R, 0), z1 = min(ciz + R, GRID - 1);
                const int wy = y1 - y0 + 1, wz = z1 - z0 + 1;
                const int nrows = wy * wz;

                if (R == 2 && !ovf) {
                    for (int q = l4; q < nrows; q += 4) {
                        int zz = z0 + q / wy, yy = y0 + q % wy;
                        int rr = (zz - gz0) * ny + (yy - gy0);
                        int st = scell[rr * 8 + (x0 - gx0)].x;
                        int en = scell[rr * 8 + (x1 - gx0)].y;
                        for (int u = st; u < en; u++) {
                            float4 pj = spt[u];
                            CAND(pj, sj[u]);
                        }
                    }
                } else {
                    for (int q = l4; q < nrows; q += 4) {
                        int zz = z0 + q / wy, yy = y0 + q % wy;
                        int crow = cbase + (zz * GRID + yy) * GRID;
                        int jst = g_range[crow + x0].x;
                        int jen = g_range[crow + x1].y;
                        for (int j2 = jst; j2 < jen; j2++) {
                            float4 pj = g_sp4[boff + j2];
                            CAND(pj, j2);
                        }
                    }
                }

                if (ginit == GATE_INF) break;
                int pall = passes;
                pall += __shfl_xor_sync(gm, pall, 1);
                pall += __shfl_xor_sync(gm, pall, 2);
                if (pall >= KNN) break;
                ginit = GATE_INF;      // rare: rescan ungated
            }

            // merge top-10 across 4 lanes; owner pops + accumulates covariance
            c00 = c01 = c02 = c11 = c12 = c22 = 0.0f;
            d10key = GATE_INF;
#pragma unroll
            for (int round = 0; round < KNN; round++) {
                unsigned long long m = best[0];
                m = min(m, __shfl_xor_sync(gm, m, 1));
                m = min(m, __shfl_xor_sync(gm, m, 2));
                bool real = ((unsigned)(m & 0xFFFFFFFFull)) != 0xFFFFFFFFu;
                if (m == best[0] && real) {
                    int j2 = (int)(unsigned)(m & 0xFFFFFFFFull);
                    float4 q = g_sp4[boff + j2];
                    float dx = q.x - pix, dy = q.y - piy, dz = q.z - piz;
                    c00 = fmaf(dx, dx, c00); c01 = fmaf(dx, dy, c01); c02 = fmaf(dx, dz, c02);
                    c11 = fmaf(dy, dy, c11); c12 = fmaf(dy, dz, c12); c22 = fmaf(dz, dz, c22);
#pragma unroll
                    for (int k = 0; k < KNN - 1; k++) best[k] = best[k + 1];
                    best[KNN - 1] = GATE_INF;
                }
                d10key = m;
            }

            // exactness: 10th dist vs distance to scanned-box interior walls
            float g = __int_as_float(0x7f800000);
            if (cix - R > 0)        g = fminf(g, pix - (float)(cix - R) * HCELL);
            if (cix + R < GRID - 1) g = fminf(g, (float)(cix + R + 1) * HCELL - pix);
            if (ciy - R > 0)        g = fminf(g, piy - (float)(ciy - R) * HCELL);
            if (ciy + R < GRID - 1) g = fminf(g, (float)(ciy + R + 1) * HCELL - piy);
            if (ciz - R > 0)        g = fminf(g, piz - (float)(ciz - R) * HCELL);
            if (ciz + R < GRID - 1) g = fminf(g, (float)(ciz + R + 1) * HCELL - piz);
            bool filled = ((unsigned)(d10key & 0xFFFFFFFFull)) != 0xFFFFFFFFu;
            float d10 = __uint_as_float((unsigned)(d10key >> 32));
            if (filled && d10 < g * g) break;
            if (R >= GRID) break;
        }

        // reduce density + covariance across 4 lanes
#pragma unroll
        for (int o = 1; o < 4; o <<= 1) {
            cnt += __shfl_xor_sync(gm, cnt, o);
            c00 += __shfl_xor_sync(gm, c00, o);
            c01 += __shfl_xor_sync(gm, c01, o);
            c02 += __shfl_xor_sync(gm, c02, o);
            c11 += __shfl_xor_sync(gm, c11, o);
            c12 += __shfl_xor_sync(gm, c12, o);
            c22 += __shfl_xor_sync(gm, c22, o);
        }

        if (l4 == 0) {
            int orig = g_sidx[boff + jp];
            c00 = __fdiv_rn(c00, 10.0f); c01 = __fdiv_rn(c01, 10.0f); c02 = __fdiv_rn(c02, 10.0f);
            c11 = __fdiv_rn(c11, 10.0f); c12 = __fdiv_rn(c12, 10.0f); c22 = __fdiv_rn(c22, 10.0f);
            float curv = curv_from_cov(c00, c01, c02, c11, c12, c22);

            double cm   = g_cacc[b][3];
            double cden = cm > 1.0 ? cm : 1.0;
            float cx = (float)(g_cacc[b][0] / cden);
            float cy = (float)(g_cacc[b][1] / cden);
            float cz = (float)(g_cacc[b][2] / cden);
            float rx = pix - cx, ry = piy - cy, rz = piz - cz;
            float distc = __fsqrt_rn(__fadd_rn(__fadd_rn(__fmul_rn(rx, rx), __fmul_rn(ry, ry)), __fmul_rn(rz, rz)));
            float horiz = __fsqrt_rn(__fadd_rn(__fmul_rn(rx, rx), __fmul_rn(ry, ry)));
            float rad   = atan2f(ry, rx);

            bool valid = cm > 0.0;
            g_geom[orig * 6 + 0] = valid ? distc : 0.0f;
            g_geom[orig * 6 + 1] = valid ? rz    : 0.0f;
            g_geom[orig * 6 + 2] = valid ? horiz : 0.0f;
            g_geom[orig * 6 + 3] = valid ? (float)cnt : 0.0f;
            g_geom[orig * 6 + 4] = valid ? curv  : 0.0f;
            g_geom[orig * 6 + 5] = valid ? rad   : 0.0f;
        }
    }
}

// ================= kernel 2: fused 2-layer MLP (f32x2 FMA, 8 cols/thread) =================
__global__ void __launch_bounds__(256) k_mlp(const float* __restrict__ feat,
                                             const float* __restrict__ W1,
                                             const float* __restrict__ b1,
                                             const float* __restrict__ W2,
                                             const float* __restrict__ b2,
                                             float* __restrict__ out) {
    extern __shared__ float sm[];
    float* sW1 = sm;             // 70*128
    float* sB1 = sm + 8960;
    float* sW2 = sm + 9088;      // 128*128
    float* sB2 = sm + 25472;
    float* sX  = sm + 25600;     // 128*72
    float* sH  = sm + 34816;     // 128*132

    int tid = threadIdx.x;
    for (int i = tid; i < 8960;  i += 256) sW1[i] = W1[i];
    for (int i = tid; i < 16384; i += 256) sW2[i] = W2[i];
    if (tid < 128) { sB1[tid] = b1[tid]; sB2[tid] = b2[tid]; }

    int m0 = blockIdx.x * 128;
    for (int i = tid; i < 128 * 64; i += 256) {
        int r = i >> 6, c = i & 63;
        sX[r * 72 + c] = feat[(m0 + r) * 64 + c];
    }
    for (int i = tid; i < 128 * 6; i += 256) {
        int r = i / 6, c = i % 6;
        sX[r * 72 + 64 + c] = g_geom[(m0 + r) * 6 + c];
    }
    __syncthreads();

    int cg = tid & 15;   // 16 col groups: cols cg*8 .. cg*8+7
    int rg = tid >> 4;   // 16 row groups: rows rg*8 .. rg*8+7

    unsigned long long acc[8][4];
#pragma unroll
    for (int r = 0; r < 8; r++)
#pragma unroll
        for (int c = 0; c < 4; c++) acc[r][c] = 0ull;

    for (int k = 0; k < 70; k++) {
        const ulonglong2* wp = (const ulonglong2*)(sW1 + k * 128 + cg * 8);
        ulonglong2 wa = wp[0], wb = wp[1];
#pragma unroll
        for (int r = 0; r < 8; r++) {
            unsigned long long xp = pack2(sX[(rg * 8 + r) * 72 + k]);
            FMA2(acc[r][0], wa.x, xp);
            FMA2(acc[r][1], wa.y, xp);
            FMA2(acc[r][2], wb.x, xp);
            FMA2(acc[r][3], wb.y, xp);
        }
    }
    {
        float4 bva = *(const float4*)(sB1 + cg * 8);
        float4 bvb = *(const float4*)(sB1 + cg * 8 + 4);
#pragma unroll
        for (int r = 0; r < 8; r++) {
            float a0, a1, a2, a3, a4, a5, a6, a7;
            unpack2(acc[r][0], a0, a1);
            unpack2(acc[r][1], a2, a3);
            unpack2(acc[r][2], a4, a5);
            unpack2(acc[r][3], a6, a7);
            float4 h0, h1;
            h0.x = fmaxf(a0 + bva.x, 0.0f); h0.y = fmaxf(a1 + bva.y, 0.0f);
            h0.z = fmaxf(a2 + bva.z, 0.0f); h0.w = fmaxf(a3 + bva.w, 0.0f);
            h1.x = fmaxf(a4 + bvb.x, 0.0f); h1.y = fmaxf(a5 + bvb.y, 0.0f);
            h1.z = fmaxf(a6 + bvb.z, 0.0f); h1.w = fmaxf(a7 + bvb.w, 0.0f);
            *(float4*)(sH + (rg * 8 + r) * 132 + cg * 8)     = h0;
            *(float4*)(sH + (rg * 8 + r) * 132 + cg * 8 + 4) = h1;
        }
    }
    __syncthreads();

#pragma unroll
    for (int r = 0; r < 8; r++)
#pragma unroll
        for (int c = 0; c < 4; c++) acc[r][c] = 0ull;

    for (int k = 0; k < 128; k++) {
        const ulonglong2* wp = (const ulonglong2*)(sW2 + k * 128 + cg * 8);
        ulonglong2 wa = wp[0], wb = wp[1];
#pragma unroll
        for (int r = 0; r < 8; r++) {
            unsigned long long hp = pack2(sH[(rg * 8 + r) * 132 + k]);
            FMA2(acc[r][0], wa.x, hp);
            FMA2(acc[r][1], wa.y, hp);
            FMA2(acc[r][2], wb.x, hp);
            FMA2(acc[r][3], wb.y, hp);
        }
    }
    {
        float4 bva = *(const float4*)(sB2 + cg * 8);
        float4 bvb = *(const float4*)(sB2 + cg * 8 + 4);
#pragma unroll
        for (int r = 0; r < 8; r++) {
            float a0, a1, a2, a3, a4, a5, a6, a7;
            unpack2(acc[r][0], a0, a1);
            unpack2(acc[r][1], a2, a3);
            unpack2(acc[r][2], a4, a5);
            unpack2(acc[r][3], a6, a7);
            float4 o0, o1;
            o0.x = fmaxf(a0 + bva.x, 0.0f); o0.y = fmaxf(a1 + bva.y, 0.0f);
            o0.z = fmaxf(a2 + bva.z, 0.0f); o0.w = fmaxf(a3 + bva.w, 0.0f);
            o1.x = fmaxf(a4 + bvb.x, 0.0f); o1.y = fmaxf(a5 + bvb.y, 0.0f);
            o1.z = fmaxf(a6 + bvb.z, 0.0f); o1.w = fmaxf(a7 + bvb.w, 0.0f);
            size_t ob = (size_t)(m0 + rg * 8 + r) * 128 + cg * 8;
            *(float4*)(out + ob)     = o0;
            *(float4*)(out + ob + 4) = o1;
        }
    }
}

// ---------------- launch ----------------
extern "C" void kernel_launch(void* const* d_in, const int* in_sizes, int n_in,
                              void* d_out, int out_size) {
    const float* points = (const float*)d_in[0];
    const float* feat   = (const float*)d_in[1];
    const void*  mask   = d_in[2];
    const float* W1     = (const float*)d_in[3];
    const float* b1     = (const float*)d_in[4];
    const float* W2     = (const float*)d_in[5];
    const float* b2     = (const float*)d_in[6];
    float* out = (float*)d_out;

    cudaFuncSetAttribute(k_mlp, cudaFuncAttributeMaxDynamicSharedMemorySize, 212992);

    k_main<<<NBLK, NTG>>>(points, mask);
    k_mlp <<<NPT / 128, 256, 206848>>>(feat, W1, b1, W2, b2, out);
}